// round 12
// baseline (speedup 1.0000x reference)
#include <cuda_runtime.h>

// Problem constants
#define BB  4
#define LL  256
#define EE  128
#define HH  8
#define DD  16
#define NUU 512
#define BLr 1024
#define TLu 4      // queries per warp (both attention types)

typedef unsigned long long u64;

// ---- packed f32x2 helpers (2 IEEE fp32 FMAs per instruction) -------------
__device__ __forceinline__ u64 pk2(float lo, float hi) {
    u64 r; asm("mov.b64 %0,{%1,%2};" : "=l"(r) : "f"(lo), "f"(hi)); return r;
}
__device__ __forceinline__ u64 bc2(float x) {
    u64 r; asm("mov.b64 %0,{%1,%1};" : "=l"(r) : "f"(x)); return r;
}
__device__ __forceinline__ void up2(u64 v, float& a, float& b) {
    asm("mov.b64 {%0,%1},%2;" : "=f"(a), "=f"(b) : "l"(v));
}
__device__ __forceinline__ u64 fma2(u64 a, u64 b, u64 c) {
    u64 r; asm("fma.rn.f32x2 %0,%1,%2,%3;" : "=l"(r) : "l"(a), "l"(b), "l"(c)); return r;
}
__device__ __forceinline__ u64 mul2(u64 a, u64 b) {
    u64 r; asm("mul.rn.f32x2 %0,%1,%2;" : "=l"(r) : "l"(a), "l"(b)); return r;
}

// ---------------- scratch (device globals; no allocation) ----------------
__device__ float g_qu[BLr*EE];
__device__ float g_qt[BLr*EE];
__device__ float g_qd[BLr*EE];
__device__ float g_kdT[BB*HH*DD*LL];    // [b][h][d][l]
__device__ float g_vdT[BB*HH*DD*LL];
__device__ float g_ktT[BB*HH*DD*LL];
__device__ float g_vtT[BB*HH*DD*LL];
__device__ float g_K0T[BB*HH*DD*NUU];   // [b][h][d][n]
__device__ float g_V0T[BB*HH*DD*NUU];
__device__ float g_CIT[BB*512*512];     // [b][j][n]
__device__ float g_att_u[BLr*EE];
__device__ float g_att_t[BLr*EE];
__device__ float g_att_d[BLr*EE];
__device__ float g_Mu[EE*EE];
__device__ float g_Mt[EE*EE];
__device__ float g_Md[EE*EE];
__device__ float g_part[6*BLr*EE];      // 3 slots x 2 K-halves
__device__ float g_s1[EE];
__device__ float g_s2[EE];

// ---------------- fused projection GEMM (packed-FMA inner loop) -----------
__global__ __launch_bounds__(256) void proj_all_kernel(
    const float* __restrict__ DU, const float* __restrict__ TA, const float* __restrict__ UU,
    const float* __restrict__ uu_w, const float* __restrict__ uu_b,
    const float* __restrict__ ta_w, const float* __restrict__ ta_b,
    const float* __restrict__ du_w, const float* __restrict__ du_b,
    const float* __restrict__ uu_ow, const float* __restrict__ ta_ow, const float* __restrict__ du_ow,
    const float* __restrict__ dim_w)
{
    __shared__ __align__(16) float As[64*36];
    __shared__ __align__(16) float Ws[32*132];
    const float* A; const float* W; const float* bias; float* C;
    int lda, M, K, wsn, wsk, tshift = 0;
    switch (blockIdx.y) {
      case 0:  A=DU;        lda=128; M=1024; K=128; W=uu_w;       wsn=128; wsk=1;  bias=uu_b;     C=g_qu;  break;
      case 1:  A=DU;        lda=128; M=1024; K=128; W=ta_w;       wsn=128; wsk=1;  bias=ta_b;     C=g_qt;  break;
      case 2:  A=DU;        lda=128; M=1024; K=128; W=du_w;       wsn=128; wsk=1;  bias=du_b;     C=g_qd;  break;
      case 3:  A=DU;        lda=128; M=1024; K=128; W=du_w+16384; wsn=128; wsk=1;  bias=du_b+128; C=g_kdT; tshift=8; break;
      case 4:  A=DU;        lda=128; M=1024; K=128; W=du_w+32768; wsn=128; wsk=1;  bias=du_b+256; C=g_vdT; tshift=8; break;
      case 5:  A=TA;        lda=128; M=1024; K=128; W=ta_w+16384; wsn=128; wsk=1;  bias=ta_b+128; C=g_ktT; tshift=8; break;
      case 6:  A=TA;        lda=128; M=1024; K=128; W=ta_w+32768; wsn=128; wsk=1;  bias=ta_b+256; C=g_vtT; tshift=8; break;
      case 7:  A=UU;        lda=126; M=2048; K=126; W=uu_w+16384; wsn=128; wsk=1;  bias=uu_b+128; C=g_K0T; tshift=9; break;
      case 8:  A=UU;        lda=126; M=2048; K=126; W=uu_w+32768; wsn=128; wsk=1;  bias=uu_b+256; C=g_V0T; tshift=9; break;
      case 9:  A=dim_w;     lda=384; M=128;  K=128; W=uu_ow;      wsn=1;   wsk=128; bias=nullptr; C=g_Mu;  break;
      case 10: A=dim_w+128; lda=384; M=128;  K=128; W=ta_ow;      wsn=1;   wsk=128; bias=nullptr; C=g_Mt;  break;
      default: A=dim_w+256; lda=384; M=128;  K=128; W=du_ow;      wsn=1;   wsk=128; bias=nullptr; C=g_Md;  break;
    }
    int row0 = blockIdx.x * 64;
    if (row0 >= M) return;
    int t  = threadIdx.x;
    int ti = t >> 5, tj = t & 31;
    u64 acc2[8][2] = {};
    for (int kc = 0; kc < K; kc += 32) {
        #pragma unroll
        for (int i = 0; i < 8; i++) {
            int idx = t + i*256;
            int r = idx >> 5, c = idx & 31;
            float v = 0.f;
            if (kc + c < K) v = A[(row0 + r) * lda + kc + c];
            As[r*36 + c] = v;
        }
        #pragma unroll
        for (int i = 0; i < 16; i++) {
            int idx = t + i*256;
            int col, kk;
            if (wsk == 1) { col = idx >> 5;  kk = idx & 31; }
            else          { col = idx & 127; kk = idx >> 7; }
            float v = 0.f;
            if (kc + kk < K) v = W[col * wsn + (kc + kk) * wsk];
            Ws[kk*132 + col] = v;
        }
        __syncthreads();
        #pragma unroll
        for (int kkb = 0; kkb < 8; kkb++) {
            ulonglong2 w0 = *(const ulonglong2*)&Ws[(kkb*4+0)*132 + (tj<<2)];
            ulonglong2 w1 = *(const ulonglong2*)&Ws[(kkb*4+1)*132 + (tj<<2)];
            ulonglong2 w2 = *(const ulonglong2*)&Ws[(kkb*4+2)*132 + (tj<<2)];
            ulonglong2 w3 = *(const ulonglong2*)&Ws[(kkb*4+3)*132 + (tj<<2)];
            #pragma unroll
            for (int i = 0; i < 8; i++) {
                float4 a4 = *(const float4*)&As[(ti*8+i)*36 + (kkb<<2)];
                u64 b0 = bc2(a4.x), b1 = bc2(a4.y), b2 = bc2(a4.z), b3 = bc2(a4.w);
                acc2[i][0] = fma2(b0, w0.x, acc2[i][0]); acc2[i][1] = fma2(b0, w0.y, acc2[i][1]);
                acc2[i][0] = fma2(b1, w1.x, acc2[i][0]); acc2[i][1] = fma2(b1, w1.y, acc2[i][1]);
                acc2[i][0] = fma2(b2, w2.x, acc2[i][0]); acc2[i][1] = fma2(b2, w2.y, acc2[i][1]);
                acc2[i][0] = fma2(b3, w3.x, acc2[i][0]); acc2[i][1] = fma2(b3, w3.y, acc2[i][1]);
            }
        }
        __syncthreads();
    }
    #pragma unroll
    for (int i = 0; i < 8; i++) {
        int r = row0 + ti*8 + i;
        float o[4];
        up2(acc2[i][0], o[0], o[1]);
        up2(acc2[i][1], o[2], o[3]);
        #pragma unroll
        for (int j = 0; j < 4; j++)
            if (bias) o[j] += bias[(tj<<2)+j];
        if (tshift) {
            int bb = r >> tshift, n = r & ((1<<tshift)-1);
            #pragma unroll
            for (int j = 0; j < 4; j++) {
                int e = (tj<<2)+j;   // e = h*16+d
                C[(((bb<<7) + e) << tshift) + n] = o[j];
            }
        } else {
            float4 v; v.x=o[0]; v.y=o[1]; v.z=o[2]; v.w=o[3];
            *(float4*)&C[r*128 + (tj<<2)] = v;
        }
    }
}

// ---------------- CIMat transpose + stats zero-init -----------------------
__global__ void transpose_ci_kernel(const float* __restrict__ CI) {
    __shared__ float s[32][33];
    int b  = blockIdx.z;
    int n0 = blockIdx.x << 5, j0 = blockIdx.y << 5;
    int tx = threadIdx.x, ty = threadIdx.y;
    if (blockIdx.x == 0 && blockIdx.y == 0 && blockIdx.z == 0) {
        int t = ty*32 + tx;
        if (t < 128) { g_s1[t] = 0.f; g_s2[t] = 0.f; }
    }
    #pragma unroll
    for (int k = 0; k < 32; k += 8)
        s[ty + k][tx] = CI[((b << 9) + n0 + ty + k) * 512 + j0 + tx];
    __syncthreads();
    #pragma unroll
    for (int k = 0; k < 32; k += 8)
        g_CIT[((b << 9) + j0 + ty + k) * 512 + n0 + tx] = s[tx][ty + k];
}

// select a[i] with i = lane (0..3) without dynamic register indexing
__device__ __forceinline__ float pick4(const float* a, int i) {
    float r = a[0];
    #pragma unroll
    for (int k = 1; k < 4; k++) r = (i == k) ? a[k] : r;
    return r;
}

// ---------------- fused attention kernel (packed FMA, merged) -------------
// grid (64, 4, 3), block 256.
// z==0: uu2du. x = (ltile<<1)|hg; warp w: head hg*4+(w>>1), queries (w&1)*4..
// z==1/2: standard MHA (ta/du), x*4 = query tile, warp w = head w.
__global__ __launch_bounds__(256,2) void attn_kernel(const float* __restrict__ uu_w) {
    __shared__ __align__(16) float sq[8*128];
    __shared__ __align__(16) float sci0[8*512];
    __shared__ __align__(16) float sci1[8*512];
    __shared__ float swv6[128], swv7[128], sa[64], sb[64];

    int z = blockIdx.z;
    int b = blockIdx.y;
    int t = threadIdx.x, w = t >> 5, lane = t & 31;

    if (z == 0) {
        int ltile = blockIdx.x >> 1;
        int hg    = blockIdx.x & 1;
        int l0    = ltile * 8;
        int h     = hg*4 + (w >> 1);
        int lw    = (w & 1) * 4;

        const float4* q4p = (const float4*)(g_qu + ((b*LL + l0) << 7));
        for (int i = t; i < 256; i += 256) ((float4*)sq)[i] = q4p[i];
        for (int i = t; i < 1024; i += 256) {
            int l = i >> 7, o = i & 127;
            ((float4*)sci0)[i] = *(const float4*)(g_CIT + ((b<<9) + l0 + l)*512 + (o<<2));
            ((float4*)sci1)[i] = *(const float4*)(g_CIT + ((b<<9) + 256 + l0 + l)*512 + (o<<2));
        }
        if (t < 128) {
            swv6[t] = uu_w[(256 + t)*128 + 126];
            swv7[t] = uu_w[(256 + t)*128 + 127];
        }
        __syncthreads();
        if (t < 64) {
            int l = t >> 3, hh = t & 7;
            float A = 0.f, Bv = 0.f;
            #pragma unroll
            for (int d = 0; d < 16; d++) {
                float qv = sq[(l<<7) + (hh<<4) + d];
                A  += qv * uu_w[(128 + (hh<<4) + d)*128 + 126];
                Bv += qv * uu_w[(128 + (hh<<4) + d)*128 + 127];
            }
            sa[t] = A; sb[t] = Bv;
        }
        __syncthreads();

        // phase 1: scores (packed pairs over n)
        u64 s2[TLu][8];
        #pragma unroll
        for (int l = 0; l < TLu; l++)
            #pragma unroll
            for (int k = 0; k < 8; k++) s2[l][k] = 0ull;
        const float* K0Th = g_K0T + (((b<<3) + h) << 4) * 512;
        #pragma unroll
        for (int d = 0; d < 16; d++) {
            u64 qb0 = bc2(sq[((lw+0)<<7) + (h<<4) + d]);
            u64 qb1 = bc2(sq[((lw+1)<<7) + (h<<4) + d]);
            u64 qb2 = bc2(sq[((lw+2)<<7) + (h<<4) + d]);
            u64 qb3 = bc2(sq[((lw+3)<<7) + (h<<4) + d]);
            const float* rp = K0Th + (d<<9) + (lane<<2);
            #pragma unroll
            for (int k4 = 0; k4 < 4; k4++) {
                ulonglong2 kv = *(const ulonglong2*)(rp + (k4<<7));
                s2[0][2*k4] = fma2(qb0, kv.x, s2[0][2*k4]); s2[0][2*k4+1] = fma2(qb0, kv.y, s2[0][2*k4+1]);
                s2[1][2*k4] = fma2(qb1, kv.x, s2[1][2*k4]); s2[1][2*k4+1] = fma2(qb1, kv.y, s2[1][2*k4+1]);
                s2[2][2*k4] = fma2(qb2, kv.x, s2[2][2*k4]); s2[2][2*k4+1] = fma2(qb2, kv.y, s2[2][2*k4+1]);
                s2[3][2*k4] = fma2(qb3, kv.x, s2[3][2*k4]); s2[3][2*k4+1] = fma2(qb3, kv.y, s2[3][2*k4+1]);
            }
        }

        // phase 2: ci correction (packed) + softmax + ci-weighted sums
        float rsum[TLu], rc0[TLu], rc1[TLu];
        u64 q25 = bc2(0.25f);
        #pragma unroll
        for (int l = 0; l < TLu; l++) {
            int lloc = lw + l;
            u64 av2 = bc2(sa[(lloc<<3) + h]), bv2 = bc2(sb[(lloc<<3) + h]);
            float m = -1e30f;
            #pragma unroll
            for (int k4 = 0; k4 < 4; k4++) {
                ulonglong2 c0 = *(const ulonglong2*)&sci0[(lloc<<9) + (k4<<7) + (lane<<2)];
                ulonglong2 c1 = *(const ulonglong2*)&sci1[(lloc<<9) + (k4<<7) + (lane<<2)];
                u64 t0 = mul2(fma2(c1.x, bv2, fma2(c0.x, av2, s2[l][2*k4])), q25);
                u64 t1 = mul2(fma2(c1.y, bv2, fma2(c0.y, av2, s2[l][2*k4+1])), q25);
                s2[l][2*k4] = t0; s2[l][2*k4+1] = t1;
                float x0,x1,x2,x3; up2(t0,x0,x1); up2(t1,x2,x3);
                m = fmaxf(m, fmaxf(fmaxf(x0,x1), fmaxf(x2,x3)));
            }
            #pragma unroll
            for (int o = 16; o > 0; o >>= 1) m = fmaxf(m, __shfl_xor_sync(0xffffffffu, m, o));
            float su = 0.f, cs0 = 0.f, cs1 = 0.f;
            #pragma unroll
            for (int k4 = 0; k4 < 4; k4++) {
                float4 c0 = *(const float4*)&sci0[(lloc<<9) + (k4<<7) + (lane<<2)];
                float4 c1 = *(const float4*)&sci1[(lloc<<9) + (k4<<7) + (lane<<2)];
                float x0,x1,x2,x3;
                up2(s2[l][2*k4], x0, x1); up2(s2[l][2*k4+1], x2, x3);
                float e0 = __expf(x0-m), e1 = __expf(x1-m);
                float e2 = __expf(x2-m), e3 = __expf(x3-m);
                s2[l][2*k4] = pk2(e0,e1); s2[l][2*k4+1] = pk2(e2,e3);
                su  += (e0+e1) + (e2+e3);
                cs0 += e0*c0.x + e1*c0.y + e2*c0.z + e3*c0.w;
                cs1 += e0*c1.x + e1*c1.y + e2*c1.z + e3*c1.w;
            }
            #pragma unroll
            for (int o = 16; o > 0; o >>= 1) {
                su  += __shfl_xor_sync(0xffffffffu, su,  o);
                cs0 += __shfl_xor_sync(0xffffffffu, cs0, o);
                cs1 += __shfl_xor_sync(0xffffffffu, cs1, o);
            }
            rsum[l] = su; rc0[l] = cs0; rc1[l] = cs1;
        }

        // phase 3: P @ V0 (packed, d in quarters of 4) + rank-2 V correction
        const float* V0Th = g_V0T + (((b<<3) + h) << 4) * 512;
        #pragma unroll
        for (int q = 0; q < 4; q++) {
            u64 acc2[TLu][4];
            #pragma unroll
            for (int l = 0; l < TLu; l++)
                #pragma unroll
                for (int dd = 0; dd < 4; dd++) acc2[l][dd] = 0ull;
            #pragma unroll
            for (int ddl = 0; ddl < 4; ddl++) {
                const float* vp = V0Th + (((q<<2)+ddl)<<9) + (lane<<2);
                #pragma unroll
                for (int k4 = 0; k4 < 4; k4++) {
                    ulonglong2 v2 = *(const ulonglong2*)(vp + (k4<<7));
                    #pragma unroll
                    for (int l = 0; l < TLu; l++) {
                        acc2[l][ddl] = fma2(s2[l][2*k4],   v2.x, acc2[l][ddl]);
                        acc2[l][ddl] = fma2(s2[l][2*k4+1], v2.y, acc2[l][ddl]);
                    }
                }
            }
            float accs[TLu][4];
            #pragma unroll
            for (int l = 0; l < TLu; l++)
                #pragma unroll
                for (int dd = 0; dd < 4; dd++) {
                    float a0, a1; up2(acc2[l][dd], a0, a1);
                    accs[l][dd] = a0 + a1;
                }
            #pragma unroll
            for (int o = 16; o > 0; o >>= 1)
                #pragma unroll
                for (int l = 0; l < TLu; l++)
                    #pragma unroll
                    for (int dd = 0; dd < 4; dd++)
                        accs[l][dd] += __shfl_xor_sync(0xffffffffu, accs[l][dd], o);
            if (lane < 4) {
                int d = (q<<2) + lane;
                #pragma unroll
                for (int l = 0; l < TLu; l++) {
                    float av = pick4(accs[l], lane);
                    float ov = (av + rc0[l]*swv6[(h<<4)+d] + rc1[l]*swv7[(h<<4)+d]) / rsum[l];
                    g_att_u[((b*LL + l0 + lw + l) << 7) + (h<<4) + d] = ov;
                }
            }
        }
    } else {
        // -------- standard MHA (ta: z==1, du: z==2), packed --------
        int zz = z - 1;
        int l0 = blockIdx.x * 4;
        int h  = w;
        const float* Q  = (zz==0) ? g_qt  : g_qd;
        const float* KT = (zz==0) ? g_ktT : g_kdT;
        const float* VT = (zz==0) ? g_vtT : g_vdT;
        float* O        = (zz==0) ? g_att_t : g_att_d;

        const float4* q4p = (const float4*)(Q + ((b*LL + l0) << 7));
        for (int i = t; i < 128; i += 256) ((float4*)sq)[i] = q4p[i];
        __syncthreads();

        u64 s2[TLu][4];
        #pragma unroll
        for (int l = 0; l < TLu; l++)
            #pragma unroll
            for (int k = 0; k < 4; k++) s2[l][k] = 0ull;
        const float* KTh = KT + (((b<<3) + h) << 4) * 256;
        #pragma unroll
        for (int d = 0; d < 16; d++) {
            u64 qb0 = bc2(sq[(0<<7) + (h<<4) + d]);
            u64 qb1 = bc2(sq[(1<<7) + (h<<4) + d]);
            u64 qb2 = bc2(sq[(2<<7) + (h<<4) + d]);
            u64 qb3 = bc2(sq[(3<<7) + (h<<4) + d]);
            const float* rp = KTh + (d<<8) + (lane<<2);
            #pragma unroll
            for (int k4 = 0; k4 < 2; k4++) {
                ulonglong2 kv = *(const ulonglong2*)(rp + (k4<<7));
                s2[0][2*k4] = fma2(qb0, kv.x, s2[0][2*k4]); s2[0][2*k4+1] = fma2(qb0, kv.y, s2[0][2*k4+1]);
                s2[1][2*k4] = fma2(qb1, kv.x, s2[1][2*k4]); s2[1][2*k4+1] = fma2(qb1, kv.y, s2[1][2*k4+1]);
                s2[2][2*k4] = fma2(qb2, kv.x, s2[2][2*k4]); s2[2][2*k4+1] = fma2(qb2, kv.y, s2[2][2*k4+1]);
                s2[3][2*k4] = fma2(qb3, kv.x, s2[3][2*k4]); s2[3][2*k4+1] = fma2(qb3, kv.y, s2[3][2*k4+1]);
            }
        }

        float rsum[TLu];
        u64 q25 = bc2(0.25f);
        #pragma unroll
        for (int l = 0; l < TLu; l++) {
            float m = -1e30f;
            #pragma unroll
            for (int k = 0; k < 4; k++) {
                s2[l][k] = mul2(s2[l][k], q25);
                float x0,x1; up2(s2[l][k], x0, x1);
                m = fmaxf(m, fmaxf(x0, x1));
            }
            #pragma unroll
            for (int o = 16; o > 0; o >>= 1) m = fmaxf(m, __shfl_xor_sync(0xffffffffu, m, o));
            float su = 0.f;
            #pragma unroll
            for (int k = 0; k < 4; k++) {
                float x0,x1; up2(s2[l][k], x0, x1);
                float e0 = __expf(x0-m), e1 = __expf(x1-m);
                s2[l][k] = pk2(e0, e1);
                su += e0 + e1;
            }
            #pragma unroll
            for (int o = 16; o > 0; o >>= 1) su += __shfl_xor_sync(0xffffffffu, su, o);
            rsum[l] = su;
        }

        const float* VTh = VT + (((b<<3) + h) << 4) * 256;
        #pragma unroll
        for (int q = 0; q < 4; q++) {
            u64 acc2[TLu][4];
            #pragma unroll
            for (int l = 0; l < TLu; l++)
                #pragma unroll
                for (int dd = 0; dd < 4; dd++) acc2[l][dd] = 0ull;
            #pragma unroll
            for (int ddl = 0; ddl < 4; ddl++) {
                const float* vp = VTh + (((q<<2)+ddl)<<8) + (lane<<2);
                #pragma unroll
                for (int k4 = 0; k4 < 2; k4++) {
                    ulonglong2 v2 = *(const ulonglong2*)(vp + (k4<<7));
                    #pragma unroll
                    for (int l = 0; l < TLu; l++) {
                        acc2[l][ddl] = fma2(s2[l][2*k4],   v2.x, acc2[l][ddl]);
                        acc2[l][ddl] = fma2(s2[l][2*k4+1], v2.y, acc2[l][ddl]);
                    }
                }
            }
            float accs[TLu][4];
            #pragma unroll
            for (int l = 0; l < TLu; l++)
                #pragma unroll
                for (int dd = 0; dd < 4; dd++) {
                    float a0, a1; up2(acc2[l][dd], a0, a1);
                    accs[l][dd] = a0 + a1;
                }
            #pragma unroll
            for (int o = 16; o > 0; o >>= 1)
                #pragma unroll
                for (int l = 0; l < TLu; l++)
                    #pragma unroll
                    for (int dd = 0; dd < 4; dd++)
                        accs[l][dd] += __shfl_xor_sync(0xffffffffu, accs[l][dd], o);
            if (lane < 4) {
                int d = (q<<2) + lane;
                #pragma unroll
                for (int l = 0; l < TLu; l++) {
                    float av = pick4(accs[l], lane);
                    O[((b*LL + l0 + l) << 7) + (h<<4) + d] = av / rsum[l];
                }
            }
        }
    }
}

// ---------------- final partial GEMM: K-split + packed FMA ----------------
__global__ __launch_bounds__(256) void final_gemm_kernel() {
    __shared__ __align__(16) float As[32*36];
    __shared__ __align__(16) float Ws[32*132];
    int sidx = blockIdx.y;
    int kz   = blockIdx.z;
    const float* A = (sidx==0) ? g_att_u : (sidx==1) ? g_att_t : g_att_d;
    const float* W = (sidx==0) ? g_Mu   : (sidx==1) ? g_Mt   : g_Md;
    float* P = g_part + (kz*3 + sidx) * (BLr*EE);
    int row0 = blockIdx.x << 5;
    int t = threadIdx.x;
    int ti = t >> 5, tj = t & 31;
    u64 acc2[4][2] = {};
    int kc0 = kz << 6;
    for (int kc = kc0; kc < kc0 + 64; kc += 32) {
        #pragma unroll
        for (int i = 0; i < 4; i++) {
            int idx = t + i*256; int r = idx>>5, c = idx&31;
            As[r*36 + c] = A[(row0 + r)*128 + kc + c];
        }
        #pragma unroll
        for (int i = 0; i < 16; i++) {
            int idx = t + i*256; int col = idx>>5, kk = idx&31;
            Ws[kk*132 + col] = W[col*128 + kc + kk];
        }
        __syncthreads();
        #pragma unroll
        for (int kkb = 0; kkb < 8; kkb++) {
            ulonglong2 w0 = *(const ulonglong2*)&Ws[(kkb*4+0)*132 + (tj<<2)];
            ulonglong2 w1 = *(const ulonglong2*)&Ws[(kkb*4+1)*132 + (tj<<2)];
            ulonglong2 w2 = *(const ulonglong2*)&Ws[(kkb*4+2)*132 + (tj<<2)];
            ulonglong2 w3 = *(const ulonglong2*)&Ws[(kkb*4+3)*132 + (tj<<2)];
            #pragma unroll
            for (int i = 0; i < 4; i++) {
                float4 a4 = *(const float4*)&As[(ti*4+i)*36 + (kkb<<2)];
                u64 b0 = bc2(a4.x), b1 = bc2(a4.y), b2 = bc2(a4.z), b3 = bc2(a4.w);
                acc2[i][0] = fma2(b0, w0.x, acc2[i][0]); acc2[i][1] = fma2(b0, w0.y, acc2[i][1]);
                acc2[i][0] = fma2(b1, w1.x, acc2[i][0]); acc2[i][1] = fma2(b1, w1.y, acc2[i][1]);
                acc2[i][0] = fma2(b2, w2.x, acc2[i][0]); acc2[i][1] = fma2(b2, w2.y, acc2[i][1]);
                acc2[i][0] = fma2(b3, w3.x, acc2[i][0]); acc2[i][1] = fma2(b3, w3.y, acc2[i][1]);
            }
        }
        __syncthreads();
    }
    #pragma unroll
    for (int i = 0; i < 4; i++) {
        int r = row0 + ti*4 + i;
        float4 o;
        up2(acc2[i][0], o.x, o.y);
        up2(acc2[i][1], o.z, o.w);
        *(float4*)&P[r*128 + (tj<<2)] = o;
    }
}

// ---------------- BN stats (coalesced, 6 partials) ------------------------
__global__ __launch_bounds__(256) void bn_stats_kernel() {
    __shared__ float sh1[256], sh2[256];
    int t = threadIdx.x;
    int base = blockIdx.x * 1024;
    float s1 = 0.f, s2 = 0.f;
    #pragma unroll
    for (int i = 0; i < 4; i++) {
        int idx = base + i*256 + t;
        float v = g_part[idx]          + g_part[131072 + idx] + g_part[262144 + idx]
                + g_part[393216 + idx] + g_part[524288 + idx] + g_part[655360 + idx];
        s1 += v; s2 += v*v;
    }
    sh1[t] = s1; sh2[t] = s2;
    __syncthreads();
    if (t < 128) {
        atomicAdd(&g_s1[t], sh1[t] + sh1[t+128]);
        atomicAdd(&g_s2[t], sh2[t] + sh2[t+128]);
    }
}

// ---------------- BN apply + ReLU (combines 6 partials on the fly) --------
__global__ __launch_bounds__(512) void bn_apply_kernel(
    const float* __restrict__ gamma, const float* __restrict__ beta,
    float* __restrict__ out)
{
    int idx = blockIdx.x*512 + threadIdx.x;
    int c = idx & 127;
    float mean = g_s1[c] * (1.f/1024.f);
    float var  = g_s2[c] * (1.f/1024.f) - mean*mean;
    float istd = rsqrtf(var + 1e-5f);
    float y = g_part[idx]          + g_part[131072 + idx] + g_part[262144 + idx]
            + g_part[393216 + idx] + g_part[524288 + idx] + g_part[655360 + idx];
    float v = (y - mean) * istd * gamma[c] + beta[c];
    out[idx] = fmaxf(v, 0.f);
}

// ---------------- host launch --------------------------------------------
extern "C" void kernel_launch(void* const* d_in, const int* in_sizes, int n_in,
                              void* d_out, int out_size) {
    const float* UU    = (const float*)d_in[0];
    const float* DU    = (const float*)d_in[1];
    const float* TA    = (const float*)d_in[2];
    const float* CI    = (const float*)d_in[3];
    const float* uu_w  = (const float*)d_in[4];
    const float* uu_b  = (const float*)d_in[5];
    const float* uu_ow = (const float*)d_in[6];
    const float* ta_w  = (const float*)d_in[8];
    const float* ta_b  = (const float*)d_in[9];
    const float* ta_ow = (const float*)d_in[10];
    const float* du_w  = (const float*)d_in[12];
    const float* du_b  = (const float*)d_in[13];
    const float* du_ow = (const float*)d_in[14];
    const float* dim_w = (const float*)d_in[16];
    const float* gamma = (const float*)d_in[18];
    const float* beta  = (const float*)d_in[19];
    float* out = (float*)d_out;

    transpose_ci_kernel<<<dim3(16,16,4), dim3(32,8)>>>(CI);
    proj_all_kernel<<<dim3(32,12), 256>>>(DU, TA, UU, uu_w, uu_b, ta_w, ta_b,
                                          du_w, du_b, uu_ow, ta_ow, du_ow, dim_w);
    attn_kernel<<<dim3(64,4,3), 256>>>(uu_w);
    final_gemm_kernel<<<dim3(32,3,2), 256>>>();
    bn_stats_kernel<<<128,256>>>();
    bn_apply_kernel<<<256,512>>>(gamma, beta, out);
}

// round 13
// speedup vs baseline: 1.0683x; 1.0683x over previous
#include <cuda_runtime.h>

// Problem constants
#define BB  4
#define LL  256
#define EE  128
#define HH  8
#define DD  16
#define NUU 512
#define BLr 1024

// ---------------- scratch (device globals; no allocation) ----------------
__device__ float g_qu[BLr*EE];
__device__ float g_qt[BLr*EE];
__device__ float g_qd[BLr*EE];
__device__ float g_kdT[BB*HH*DD*LL];    // [b][h][d][l]
__device__ float g_vdT[BB*HH*DD*LL];
__device__ float g_ktT[BB*HH*DD*LL];
__device__ float g_vtT[BB*HH*DD*LL];
__device__ float g_K0T[BB*HH*DD*NUU];   // [b][h][d][n]
__device__ float g_V0T[BB*HH*DD*NUU];
__device__ float g_CIT[BB*512*512];     // [b][j][n]
__device__ float g_att_u[BLr*EE];
__device__ float g_att_t[BLr*EE];
__device__ float g_att_d[BLr*EE];
__device__ float g_Mu[EE*EE];
__device__ float g_Mt[EE*EE];
__device__ float g_Md[EE*EE];
__device__ float g_part[6*BLr*EE];      // 3 slots x 2 K-halves
__device__ float g_s1[EE];
__device__ float g_s2[EE];

// ---------------- fused projection GEMM (R10 proven version) --------------
__global__ __launch_bounds__(256) void proj_all_kernel(
    const float* __restrict__ DU, const float* __restrict__ TA, const float* __restrict__ UU,
    const float* __restrict__ uu_w, const float* __restrict__ uu_b,
    const float* __restrict__ ta_w, const float* __restrict__ ta_b,
    const float* __restrict__ du_w, const float* __restrict__ du_b,
    const float* __restrict__ uu_ow, const float* __restrict__ ta_ow, const float* __restrict__ du_ow,
    const float* __restrict__ dim_w)
{
    __shared__ __align__(16) float As[64*36];
    __shared__ __align__(16) float Ws[32*132];
    const float* A; const float* W; const float* bias; float* C;
    int lda, M, K, wsn, wsk, tshift = 0;
    switch (blockIdx.y) {
      case 0:  A=DU;        lda=128; M=1024; K=128; W=uu_w;       wsn=128; wsk=1;  bias=uu_b;     C=g_qu;  break;
      case 1:  A=DU;        lda=128; M=1024; K=128; W=ta_w;       wsn=128; wsk=1;  bias=ta_b;     C=g_qt;  break;
      case 2:  A=DU;        lda=128; M=1024; K=128; W=du_w;       wsn=128; wsk=1;  bias=du_b;     C=g_qd;  break;
      case 3:  A=DU;        lda=128; M=1024; K=128; W=du_w+16384; wsn=128; wsk=1;  bias=du_b+128; C=g_kdT; tshift=8; break;
      case 4:  A=DU;        lda=128; M=1024; K=128; W=du_w+32768; wsn=128; wsk=1;  bias=du_b+256; C=g_vdT; tshift=8; break;
      case 5:  A=TA;        lda=128; M=1024; K=128; W=ta_w+16384; wsn=128; wsk=1;  bias=ta_b+128; C=g_ktT; tshift=8; break;
      case 6:  A=TA;        lda=128; M=1024; K=128; W=ta_w+32768; wsn=128; wsk=1;  bias=ta_b+256; C=g_vtT; tshift=8; break;
      case 7:  A=UU;        lda=126; M=2048; K=126; W=uu_w+16384; wsn=128; wsk=1;  bias=uu_b+128; C=g_K0T; tshift=9; break;
      case 8:  A=UU;        lda=126; M=2048; K=126; W=uu_w+32768; wsn=128; wsk=1;  bias=uu_b+256; C=g_V0T; tshift=9; break;
      case 9:  A=dim_w;     lda=384; M=128;  K=128; W=uu_ow;      wsn=1;   wsk=128; bias=nullptr; C=g_Mu;  break;
      case 10: A=dim_w+128; lda=384; M=128;  K=128; W=ta_ow;      wsn=1;   wsk=128; bias=nullptr; C=g_Mt;  break;
      default: A=dim_w+256; lda=384; M=128;  K=128; W=du_ow;      wsn=1;   wsk=128; bias=nullptr; C=g_Md;  break;
    }
    int row0 = blockIdx.x * 64;
    if (row0 >= M) return;
    int t  = threadIdx.x;
    int ti = t >> 5, tj = t & 31;
    float acc[8][4] = {};
    for (int kc = 0; kc < K; kc += 32) {
        #pragma unroll
        for (int i = 0; i < 8; i++) {
            int idx = t + i*256;
            int r = idx >> 5, c = idx & 31;
            float v = 0.f;
            if (kc + c < K) v = A[(row0 + r) * lda + kc + c];
            As[r*36 + c] = v;
        }
        #pragma unroll
        for (int i = 0; i < 16; i++) {
            int idx = t + i*256;
            int col, kk;
            if (wsk == 1) { col = idx >> 5;  kk = idx & 31; }
            else          { col = idx & 127; kk = idx >> 7; }
            float v = 0.f;
            if (kc + kk < K) v = W[col * wsn + (kc + kk) * wsk];
            Ws[kk*132 + col] = v;
        }
        __syncthreads();
        #pragma unroll
        for (int kkb = 0; kkb < 8; kkb++) {
            float4 w0 = *(const float4*)&Ws[(kkb*4+0)*132 + (tj<<2)];
            float4 w1 = *(const float4*)&Ws[(kkb*4+1)*132 + (tj<<2)];
            float4 w2 = *(const float4*)&Ws[(kkb*4+2)*132 + (tj<<2)];
            float4 w3 = *(const float4*)&Ws[(kkb*4+3)*132 + (tj<<2)];
            #pragma unroll
            for (int i = 0; i < 8; i++) {
                float4 a4 = *(const float4*)&As[(ti*8+i)*36 + (kkb<<2)];
                acc[i][0] += a4.x*w0.x + a4.y*w1.x + a4.z*w2.x + a4.w*w3.x;
                acc[i][1] += a4.x*w0.y + a4.y*w1.y + a4.z*w2.y + a4.w*w3.y;
                acc[i][2] += a4.x*w0.z + a4.y*w1.z + a4.z*w2.z + a4.w*w3.z;
                acc[i][3] += a4.x*w0.w + a4.y*w1.w + a4.z*w2.w + a4.w*w3.w;
            }
        }
        __syncthreads();
    }
    #pragma unroll
    for (int i = 0; i < 8; i++) {
        int r = row0 + ti*8 + i;
        float o[4];
        #pragma unroll
        for (int j = 0; j < 4; j++) {
            o[j] = acc[i][j];
            if (bias) o[j] += bias[(tj<<2)+j];
        }
        if (tshift) {
            int bb = r >> tshift, n = r & ((1<<tshift)-1);
            #pragma unroll
            for (int j = 0; j < 4; j++) {
                int e = (tj<<2)+j;   // e = h*16+d
                C[(((bb<<7) + e) << tshift) + n] = o[j];
            }
        } else {
            float4 v; v.x=o[0]; v.y=o[1]; v.z=o[2]; v.w=o[3];
            *(float4*)&C[r*128 + (tj<<2)] = v;
        }
    }
}

// ---------------- CIMat transpose + stats zero-init -----------------------
__global__ void transpose_ci_kernel(const float* __restrict__ CI) {
    __shared__ float s[32][33];
    int b  = blockIdx.z;
    int n0 = blockIdx.x << 5, j0 = blockIdx.y << 5;
    int tx = threadIdx.x, ty = threadIdx.y;
    if (blockIdx.x == 0 && blockIdx.y == 0 && blockIdx.z == 0) {
        int t = ty*32 + tx;
        if (t < 128) { g_s1[t] = 0.f; g_s2[t] = 0.f; }
    }
    #pragma unroll
    for (int k = 0; k < 32; k += 8)
        s[ty + k][tx] = CI[((b << 9) + n0 + ty + k) * 512 + j0 + tx];
    __syncthreads();
    #pragma unroll
    for (int k = 0; k < 32; k += 8)
        g_CIT[((b << 9) + j0 + ty + k) * 512 + n0 + tx] = s[tx][ty + k];
}

// select a[i] with i = lane (0..3) without dynamic register indexing
__device__ __forceinline__ float pick4(const float* a, int i) {
    float r = a[0];
    #pragma unroll
    for (int k = 1; k < 4; k++) r = (i == k) ? a[k] : r;
    return r;
}

// ---------------- fused attention kernel (scalar, higher occupancy) -------
// grid (128, 4, 3), block 256, 3 blocks/SM.
// z==0: uu2du, 2 queries/warp. x = (ltile<<1)|hg, ltile covers 4 queries;
//        warp w: head hg*4+(w>>1), queries (w&1)*2 .. +1.
// z==1/2: standard MHA (ta/du), x<64 only; x*4 = query tile, warp w = head w.
__global__ __launch_bounds__(256,3) void attn_kernel(const float* __restrict__ uu_w) {
    __shared__ __align__(16) float sq[4*128];
    __shared__ __align__(16) float sci0[4*512];
    __shared__ __align__(16) float sci1[4*512];
    __shared__ float swv6[128], swv7[128], sa[32], sb[32];

    int z = blockIdx.z;
    int b = blockIdx.y;
    int t = threadIdx.x, w = t >> 5, lane = t & 31;

    if (z == 0) {
        int ltile = blockIdx.x >> 1;       // 0..63 -> 4 queries each
        int hg    = blockIdx.x & 1;
        int l0    = ltile * 4;
        int h     = hg*4 + (w >> 1);
        int lw    = (w & 1) * 2;           // local query offset (0 or 2)

        const float4* q4p = (const float4*)(g_qu + ((b*LL + l0) << 7));
        for (int i = t; i < 128; i += 256) ((float4*)sq)[i] = q4p[i];
        for (int i = t; i < 512; i += 256) {
            int l = i >> 7, o = i & 127;
            ((float4*)sci0)[i] = *(const float4*)(g_CIT + ((b<<9) + l0 + l)*512 + (o<<2));
            ((float4*)sci1)[i] = *(const float4*)(g_CIT + ((b<<9) + 256 + l0 + l)*512 + (o<<2));
        }
        if (t < 128) {
            swv6[t] = uu_w[(256 + t)*128 + 126];
            swv7[t] = uu_w[(256 + t)*128 + 127];
        }
        __syncthreads();
        if (t < 32) {
            int l = t >> 3, hh = t & 7;
            float A = 0.f, Bv = 0.f;
            #pragma unroll
            for (int d = 0; d < 16; d++) {
                float qv = sq[(l<<7) + (hh<<4) + d];
                A  += qv * uu_w[(128 + (hh<<4) + d)*128 + 126];
                Bv += qv * uu_w[(128 + (hh<<4) + d)*128 + 127];
            }
            sa[t] = A; sb[t] = Bv;
        }
        __syncthreads();

        // phase 1: scores, n = k4*128 + lane*4 + j
        float s[2][16];
        #pragma unroll
        for (int l = 0; l < 2; l++)
            #pragma unroll
            for (int k = 0; k < 16; k++) s[l][k] = 0.f;
        const float* K0Th = g_K0T + (((b<<3) + h) << 4) * 512;
        #pragma unroll
        for (int d = 0; d < 16; d++) {
            float q0 = sq[((lw+0)<<7) + (h<<4) + d];
            float q1 = sq[((lw+1)<<7) + (h<<4) + d];
            const float* rp = K0Th + (d<<9) + (lane<<2);
            #pragma unroll
            for (int k4 = 0; k4 < 4; k4++) {
                float4 kv = *(const float4*)(rp + (k4<<7));
                s[0][4*k4+0]+=q0*kv.x; s[0][4*k4+1]+=q0*kv.y; s[0][4*k4+2]+=q0*kv.z; s[0][4*k4+3]+=q0*kv.w;
                s[1][4*k4+0]+=q1*kv.x; s[1][4*k4+1]+=q1*kv.y; s[1][4*k4+2]+=q1*kv.z; s[1][4*k4+3]+=q1*kv.w;
            }
        }

        // phase 2: ci correction + softmax + ci-weighted sums
        float rsum[2], rc0[2], rc1[2];
        #pragma unroll
        for (int l = 0; l < 2; l++) {
            int lloc = lw + l;
            float av = sa[(lloc<<3) + h], bv = sb[(lloc<<3) + h];
            float m = -1e30f;
            #pragma unroll
            for (int k4 = 0; k4 < 4; k4++) {
                float4 c0 = *(const float4*)&sci0[(lloc<<9) + (k4<<7) + (lane<<2)];
                float4 c1 = *(const float4*)&sci1[(lloc<<9) + (k4<<7) + (lane<<2)];
                float* sp = &s[l][k4<<2];
                sp[0] = (sp[0] + c0.x*av + c1.x*bv) * 0.25f;
                sp[1] = (sp[1] + c0.y*av + c1.y*bv) * 0.25f;
                sp[2] = (sp[2] + c0.z*av + c1.z*bv) * 0.25f;
                sp[3] = (sp[3] + c0.w*av + c1.w*bv) * 0.25f;
                m = fmaxf(m, fmaxf(fmaxf(sp[0], sp[1]), fmaxf(sp[2], sp[3])));
            }
            #pragma unroll
            for (int o = 16; o > 0; o >>= 1) m = fmaxf(m, __shfl_xor_sync(0xffffffffu, m, o));
            float su = 0.f, cs0 = 0.f, cs1 = 0.f;
            #pragma unroll
            for (int k4 = 0; k4 < 4; k4++) {
                float4 c0 = *(const float4*)&sci0[(lloc<<9) + (k4<<7) + (lane<<2)];
                float4 c1 = *(const float4*)&sci1[(lloc<<9) + (k4<<7) + (lane<<2)];
                float* sp = &s[l][k4<<2];
                float e0 = __expf(sp[0]-m), e1 = __expf(sp[1]-m);
                float e2 = __expf(sp[2]-m), e3 = __expf(sp[3]-m);
                sp[0]=e0; sp[1]=e1; sp[2]=e2; sp[3]=e3;
                su  += (e0+e1) + (e2+e3);
                cs0 += e0*c0.x + e1*c0.y + e2*c0.z + e3*c0.w;
                cs1 += e0*c1.x + e1*c1.y + e2*c1.z + e3*c1.w;
            }
            #pragma unroll
            for (int o = 16; o > 0; o >>= 1) {
                su  += __shfl_xor_sync(0xffffffffu, su,  o);
                cs0 += __shfl_xor_sync(0xffffffffu, cs0, o);
                cs1 += __shfl_xor_sync(0xffffffffu, cs1, o);
            }
            rsum[l] = su; rc0[l] = cs0; rc1[l] = cs1;
        }

        // phase 3: P @ V0 (d in quarters of 4) + rank-2 V correction
        const float* V0Th = g_V0T + (((b<<3) + h) << 4) * 512;
        #pragma unroll
        for (int q = 0; q < 4; q++) {
            float acc[2][4];
            #pragma unroll
            for (int l = 0; l < 2; l++)
                #pragma unroll
                for (int dd = 0; dd < 4; dd++) acc[l][dd] = 0.f;
            #pragma unroll
            for (int ddl = 0; ddl < 4; ddl++) {
                const float* vp = V0Th + (((q<<2)+ddl)<<9) + (lane<<2);
                #pragma unroll
                for (int k4 = 0; k4 < 4; k4++) {
                    float4 v4 = *(const float4*)(vp + (k4<<7));
                    #pragma unroll
                    for (int l = 0; l < 2; l++) {
                        float* sp = &s[l][k4<<2];
                        acc[l][ddl] += sp[0]*v4.x + sp[1]*v4.y + sp[2]*v4.z + sp[3]*v4.w;
                    }
                }
            }
            #pragma unroll
            for (int o = 16; o > 0; o >>= 1)
                #pragma unroll
                for (int l = 0; l < 2; l++)
                    #pragma unroll
                    for (int dd = 0; dd < 4; dd++)
                        acc[l][dd] += __shfl_xor_sync(0xffffffffu, acc[l][dd], o);
            if (lane < 4) {
                int d = (q<<2) + lane;
                #pragma unroll
                for (int l = 0; l < 2; l++) {
                    float av = pick4(acc[l], lane);
                    float ov = (av + rc0[l]*swv6[(h<<4)+d] + rc1[l]*swv7[(h<<4)+d]) / rsum[l];
                    g_att_u[((b*LL + l0 + lw + l) << 7) + (h<<4) + d] = ov;
                }
            }
        }
    } else {
        // -------- standard MHA (ta: z==1, du: z==2) --------
        if (blockIdx.x >= 64) return;
        int l0 = blockIdx.x * 4;
        int h  = w;
        const float* Q  = (z==1) ? g_qt  : g_qd;
        const float* KT = (z==1) ? g_ktT : g_kdT;
        const float* VT = (z==1) ? g_vtT : g_vdT;
        float* O        = (z==1) ? g_att_t : g_att_d;

        const float4* q4p = (const float4*)(Q + ((b*LL + l0) << 7));
        for (int i = t; i < 128; i += 256) ((float4*)sq)[i] = q4p[i];
        __syncthreads();

        float s[4][8];
        #pragma unroll
        for (int l = 0; l < 4; l++)
            #pragma unroll
            for (int k = 0; k < 8; k++) s[l][k] = 0.f;
        const float* KTh = KT + (((b<<3) + h) << 4) * 256;
        #pragma unroll
        for (int d = 0; d < 16; d++) {
            float q0 = sq[(0<<7) + (h<<4) + d];
            float q1 = sq[(1<<7) + (h<<4) + d];
            float q2 = sq[(2<<7) + (h<<4) + d];
            float q3 = sq[(3<<7) + (h<<4) + d];
            const float* rp = KTh + (d<<8) + (lane<<2);
            #pragma unroll
            for (int k4 = 0; k4 < 2; k4++) {
                float4 kv = *(const float4*)(rp + (k4<<7));
                s[0][4*k4+0]+=q0*kv.x; s[0][4*k4+1]+=q0*kv.y; s[0][4*k4+2]+=q0*kv.z; s[0][4*k4+3]+=q0*kv.w;
                s[1][4*k4+0]+=q1*kv.x; s[1][4*k4+1]+=q1*kv.y; s[1][4*k4+2]+=q1*kv.z; s[1][4*k4+3]+=q1*kv.w;
                s[2][4*k4+0]+=q2*kv.x; s[2][4*k4+1]+=q2*kv.y; s[2][4*k4+2]+=q2*kv.z; s[2][4*k4+3]+=q2*kv.w;
                s[3][4*k4+0]+=q3*kv.x; s[3][4*k4+1]+=q3*kv.y; s[3][4*k4+2]+=q3*kv.z; s[3][4*k4+3]+=q3*kv.w;
            }
        }
        float rsum[4];
        #pragma unroll
        for (int l = 0; l < 4; l++) {
            float m = -1e30f;
            #pragma unroll
            for (int k = 0; k < 8; k++) { s[l][k] *= 0.25f; m = fmaxf(m, s[l][k]); }
            #pragma unroll
            for (int o = 16; o > 0; o >>= 1) m = fmaxf(m, __shfl_xor_sync(0xffffffffu, m, o));
            float su = 0.f;
            #pragma unroll
            for (int k = 0; k < 8; k++) { float e = __expf(s[l][k]-m); s[l][k] = e; su += e; }
            #pragma unroll
            for (int o = 16; o > 0; o >>= 1) su += __shfl_xor_sync(0xffffffffu, su, o);
            rsum[l] = su;
        }
        const float* VTh = VT + (((b<<3) + h) << 4) * 256;
        #pragma unroll
        for (int q = 0; q < 4; q++) {
            float acc[4][4];
            #pragma unroll
            for (int l = 0; l < 4; l++)
                #pragma unroll
                for (int dd = 0; dd < 4; dd++) acc[l][dd] = 0.f;
            #pragma unroll
            for (int ddl = 0; ddl < 4; ddl++) {
                const float* vp = VTh + (((q<<2)+ddl)<<8) + (lane<<2);
                #pragma unroll
                for (int k4 = 0; k4 < 2; k4++) {
                    float4 v4 = *(const float4*)(vp + (k4<<7));
                    #pragma unroll
                    for (int l = 0; l < 4; l++) {
                        float* sp = &s[l][k4<<2];
                        acc[l][ddl] += sp[0]*v4.x + sp[1]*v4.y + sp[2]*v4.z + sp[3]*v4.w;
                    }
                }
            }
            #pragma unroll
            for (int o = 16; o > 0; o >>= 1)
                #pragma unroll
                for (int l = 0; l < 4; l++)
                    #pragma unroll
                    for (int dd = 0; dd < 4; dd++)
                        acc[l][dd] += __shfl_xor_sync(0xffffffffu, acc[l][dd], o);
            if (lane < 4) {
                int d = (q<<2) + lane;
                #pragma unroll
                for (int l = 0; l < 4; l++) {
                    float av = pick4(acc[l], lane);
                    O[((b*LL + l0 + l) << 7) + (h<<4) + d] = av / rsum[l];
                }
            }
        }
    }
}

// ---------------- final partial GEMM: K-split + vectorized (R10) ----------
__global__ __launch_bounds__(256) void final_gemm_kernel() {
    __shared__ __align__(16) float As[32*36];
    __shared__ __align__(16) float Ws[32*132];
    int sidx = blockIdx.y;
    int kz   = blockIdx.z;
    const float* A = (sidx==0) ? g_att_u : (sidx==1) ? g_att_t : g_att_d;
    const float* W = (sidx==0) ? g_Mu   : (sidx==1) ? g_Mt   : g_Md;
    float* P = g_part + (kz*3 + sidx) * (BLr*EE);
    int row0 = blockIdx.x << 5;
    int t = threadIdx.x;
    int ti = t >> 5, tj = t & 31;
    float acc[4][4] = {};
    int kc0 = kz << 6;
    for (int kc = kc0; kc < kc0 + 64; kc += 32) {
        #pragma unroll
        for (int i = 0; i < 4; i++) {
            int idx = t + i*256; int r = idx>>5, c = idx&31;
            As[r*36 + c] = A[(row0 + r)*128 + kc + c];
        }
        #pragma unroll
        for (int i = 0; i < 16; i++) {
            int idx = t + i*256; int col = idx>>5, kk = idx&31;
            Ws[kk*132 + col] = W[col*128 + kc + kk];
        }
        __syncthreads();
        #pragma unroll
        for (int kkb = 0; kkb < 8; kkb++) {
            float4 w0 = *(const float4*)&Ws[(kkb*4+0)*132 + (tj<<2)];
            float4 w1 = *(const float4*)&Ws[(kkb*4+1)*132 + (tj<<2)];
            float4 w2 = *(const float4*)&Ws[(kkb*4+2)*132 + (tj<<2)];
            float4 w3 = *(const float4*)&Ws[(kkb*4+3)*132 + (tj<<2)];
            #pragma unroll
            for (int i = 0; i < 4; i++) {
                float4 a4 = *(const float4*)&As[(ti*4+i)*36 + (kkb<<2)];
                acc[i][0] += a4.x*w0.x + a4.y*w1.x + a4.z*w2.x + a4.w*w3.x;
                acc[i][1] += a4.x*w0.y + a4.y*w1.y + a4.z*w2.y + a4.w*w3.y;
                acc[i][2] += a4.x*w0.z + a4.y*w1.z + a4.z*w2.z + a4.w*w3.z;
                acc[i][3] += a4.x*w0.w + a4.y*w1.w + a4.z*w2.w + a4.w*w3.w;
            }
        }
        __syncthreads();
    }
    #pragma unroll
    for (int i = 0; i < 4; i++) {
        int r = row0 + ti*4 + i;
        float4 o;
        o.x = acc[i][0]; o.y = acc[i][1]; o.z = acc[i][2]; o.w = acc[i][3];
        *(float4*)&P[r*128 + (tj<<2)] = o;
    }
}

// ---------------- BN stats (coalesced, 6 partials) ------------------------
__global__ __launch_bounds__(256) void bn_stats_kernel() {
    __shared__ float sh1[256], sh2[256];
    int t = threadIdx.x;
    int base = blockIdx.x * 1024;
    float s1 = 0.f, s2 = 0.f;
    #pragma unroll
    for (int i = 0; i < 4; i++) {
        int idx = base + i*256 + t;
        float v = g_part[idx]          + g_part[131072 + idx] + g_part[262144 + idx]
                + g_part[393216 + idx] + g_part[524288 + idx] + g_part[655360 + idx];
        s1 += v; s2 += v*v;
    }
    sh1[t] = s1; sh2[t] = s2;
    __syncthreads();
    if (t < 128) {
        atomicAdd(&g_s1[t], sh1[t] + sh1[t+128]);
        atomicAdd(&g_s2[t], sh2[t] + sh2[t+128]);
    }
}

// ---------------- BN apply + ReLU (combines 6 partials on the fly) --------
__global__ __launch_bounds__(512) void bn_apply_kernel(
    const float* __restrict__ gamma, const float* __restrict__ beta,
    float* __restrict__ out)
{
    int idx = blockIdx.x*512 + threadIdx.x;
    int c = idx & 127;
    float mean = g_s1[c] * (1.f/1024.f);
    float var  = g_s2[c] * (1.f/1024.f) - mean*mean;
    float istd = rsqrtf(var + 1e-5f);
    float y = g_part[idx]          + g_part[131072 + idx] + g_part[262144 + idx]
            + g_part[393216 + idx] + g_part[524288 + idx] + g_part[655360 + idx];
    float v = (y - mean) * istd * gamma[c] + beta[c];
    out[idx] = fmaxf(v, 0.f);
}

// ---------------- host launch --------------------------------------------
extern "C" void kernel_launch(void* const* d_in, const int* in_sizes, int n_in,
                              void* d_out, int out_size) {
    const float* UU    = (const float*)d_in[0];
    const float* DU    = (const float*)d_in[1];
    const float* TA    = (const float*)d_in[2];
    const float* CI    = (const float*)d_in[3];
    const float* uu_w  = (const float*)d_in[4];
    const float* uu_b  = (const float*)d_in[5];
    const float* uu_ow = (const float*)d_in[6];
    const float* ta_w  = (const float*)d_in[8];
    const float* ta_b  = (const float*)d_in[9];
    const float* ta_ow = (const float*)d_in[10];
    const float* du_w  = (const float*)d_in[12];
    const float* du_b  = (const float*)d_in[13];
    const float* du_ow = (const float*)d_in[14];
    const float* dim_w = (const float*)d_in[16];
    const float* gamma = (const float*)d_in[18];
    const float* beta  = (const float*)d_in[19];
    float* out = (float*)d_out;

    transpose_ci_kernel<<<dim3(16,16,4), dim3(32,8)>>>(CI);
    proj_all_kernel<<<dim3(32,12), 256>>>(DU, TA, UU, uu_w, uu_b, ta_w, ta_b,
                                          du_w, du_b, uu_ow, ta_ow, du_ow, dim_w);
    attn_kernel<<<dim3(128,4,3), 256>>>(uu_w);
    final_gemm_kernel<<<dim3(32,3,2), 256>>>();
    bn_stats_kernel<<<128,256>>>();
    bn_apply_kernel<<<256,512>>>(gamma, beta, out);
}

// round 14
// speedup vs baseline: 1.1506x; 1.0770x over previous
#include <cuda_runtime.h>

// Problem constants
#define BB  4
#define LL  256
#define EE  128
#define HH  8
#define DD  16
#define NUU 512
#define BLr 1024
#define TLu 4      // queries per warp (both attention types)

// ---------------- scratch (device globals; no allocation) ----------------
__device__ float g_qu[BLr*EE];
__device__ float g_qt[BLr*EE];
__device__ float g_qd[BLr*EE];
__device__ float g_kdT[BB*HH*DD*LL];    // [b][h][d][l]
__device__ float g_vdT[BB*HH*DD*LL];
__device__ float g_ktT[BB*HH*DD*LL];
__device__ float g_vtT[BB*HH*DD*LL];
__device__ float g_K0T[BB*HH*DD*NUU];   // [b][h][d][n]
__device__ float g_V0T[BB*HH*DD*NUU];
__device__ float g_att_u[BLr*EE];
__device__ float g_att_t[BLr*EE];
__device__ float g_att_d[BLr*EE];
__device__ float g_Mu[EE*EE];
__device__ float g_Mt[EE*EE];
__device__ float g_Md[EE*EE];
__device__ float g_part[6*BLr*EE];      // 3 slots x 2 K-halves
__device__ float g_s1[EE];
__device__ float g_s2[EE];

// ---------------- fused projection GEMM (R10 proven version) --------------
// Idle block (y==9, x==31) zero-inits the BN stats accumulators.
__global__ __launch_bounds__(256) void proj_all_kernel(
    const float* __restrict__ DU, const float* __restrict__ TA, const float* __restrict__ UU,
    const float* __restrict__ uu_w, const float* __restrict__ uu_b,
    const float* __restrict__ ta_w, const float* __restrict__ ta_b,
    const float* __restrict__ du_w, const float* __restrict__ du_b,
    const float* __restrict__ uu_ow, const float* __restrict__ ta_ow, const float* __restrict__ du_ow,
    const float* __restrict__ dim_w)
{
    __shared__ __align__(16) float As[64*36];
    __shared__ __align__(16) float Ws[32*132];
    const float* A; const float* W; const float* bias; float* C;
    int lda, M, K, wsn, wsk, tshift = 0;
    switch (blockIdx.y) {
      case 0:  A=DU;        lda=128; M=1024; K=128; W=uu_w;       wsn=128; wsk=1;  bias=uu_b;     C=g_qu;  break;
      case 1:  A=DU;        lda=128; M=1024; K=128; W=ta_w;       wsn=128; wsk=1;  bias=ta_b;     C=g_qt;  break;
      case 2:  A=DU;        lda=128; M=1024; K=128; W=du_w;       wsn=128; wsk=1;  bias=du_b;     C=g_qd;  break;
      case 3:  A=DU;        lda=128; M=1024; K=128; W=du_w+16384; wsn=128; wsk=1;  bias=du_b+128; C=g_kdT; tshift=8; break;
      case 4:  A=DU;        lda=128; M=1024; K=128; W=du_w+32768; wsn=128; wsk=1;  bias=du_b+256; C=g_vdT; tshift=8; break;
      case 5:  A=TA;        lda=128; M=1024; K=128; W=ta_w+16384; wsn=128; wsk=1;  bias=ta_b+128; C=g_ktT; tshift=8; break;
      case 6:  A=TA;        lda=128; M=1024; K=128; W=ta_w+32768; wsn=128; wsk=1;  bias=ta_b+256; C=g_vtT; tshift=8; break;
      case 7:  A=UU;        lda=126; M=2048; K=126; W=uu_w+16384; wsn=128; wsk=1;  bias=uu_b+128; C=g_K0T; tshift=9; break;
      case 8:  A=UU;        lda=126; M=2048; K=126; W=uu_w+32768; wsn=128; wsk=1;  bias=uu_b+256; C=g_V0T; tshift=9; break;
      case 9:  A=dim_w;     lda=384; M=128;  K=128; W=uu_ow;      wsn=1;   wsk=128; bias=nullptr; C=g_Mu;  break;
      case 10: A=dim_w+128; lda=384; M=128;  K=128; W=ta_ow;      wsn=1;   wsk=128; bias=nullptr; C=g_Mt;  break;
      default: A=dim_w+256; lda=384; M=128;  K=128; W=du_ow;      wsn=1;   wsk=128; bias=nullptr; C=g_Md;  break;
    }
    int row0 = blockIdx.x * 64;
    int t  = threadIdx.x;
    if (row0 >= M) {
        if (blockIdx.y == 9 && blockIdx.x == 31 && t < 128) { g_s1[t] = 0.f; g_s2[t] = 0.f; }
        return;
    }
    int ti = t >> 5, tj = t & 31;
    float acc[8][4] = {};
    for (int kc = 0; kc < K; kc += 32) {
        #pragma unroll
        for (int i = 0; i < 8; i++) {
            int idx = t + i*256;
            int r = idx >> 5, c = idx & 31;
            float v = 0.f;
            if (kc + c < K) v = A[(row0 + r) * lda + kc + c];
            As[r*36 + c] = v;
        }
        #pragma unroll
        for (int i = 0; i < 16; i++) {
            int idx = t + i*256;
            int col, kk;
            if (wsk == 1) { col = idx >> 5;  kk = idx & 31; }
            else          { col = idx & 127; kk = idx >> 7; }
            float v = 0.f;
            if (kc + kk < K) v = W[col * wsn + (kc + kk) * wsk];
            Ws[kk*132 + col] = v;
        }
        __syncthreads();
        #pragma unroll
        for (int kkb = 0; kkb < 8; kkb++) {
            float4 w0 = *(const float4*)&Ws[(kkb*4+0)*132 + (tj<<2)];
            float4 w1 = *(const float4*)&Ws[(kkb*4+1)*132 + (tj<<2)];
            float4 w2 = *(const float4*)&Ws[(kkb*4+2)*132 + (tj<<2)];
            float4 w3 = *(const float4*)&Ws[(kkb*4+3)*132 + (tj<<2)];
            #pragma unroll
            for (int i = 0; i < 8; i++) {
                float4 a4 = *(const float4*)&As[(ti*8+i)*36 + (kkb<<2)];
                acc[i][0] += a4.x*w0.x + a4.y*w1.x + a4.z*w2.x + a4.w*w3.x;
                acc[i][1] += a4.x*w0.y + a4.y*w1.y + a4.z*w2.y + a4.w*w3.y;
                acc[i][2] += a4.x*w0.z + a4.y*w1.z + a4.z*w2.z + a4.w*w3.z;
                acc[i][3] += a4.x*w0.w + a4.y*w1.w + a4.z*w2.w + a4.w*w3.w;
            }
        }
        __syncthreads();
    }
    #pragma unroll
    for (int i = 0; i < 8; i++) {
        int r = row0 + ti*8 + i;
        float o[4];
        #pragma unroll
        for (int j = 0; j < 4; j++) {
            o[j] = acc[i][j];
            if (bias) o[j] += bias[(tj<<2)+j];
        }
        if (tshift) {
            int bb = r >> tshift, n = r & ((1<<tshift)-1);
            #pragma unroll
            for (int j = 0; j < 4; j++) {
                int e = (tj<<2)+j;   // e = h*16+d
                C[(((bb<<7) + e) << tshift) + n] = o[j];
            }
        } else {
            float4 v; v.x=o[0]; v.y=o[1]; v.z=o[2]; v.w=o[3];
            *(float4*)&C[r*128 + (tj<<2)] = v;
        }
    }
}

// select a[i] with i = lane (0..7) without dynamic register indexing
__device__ __forceinline__ float pick8(const float* a, int i) {
    float r = a[0];
    #pragma unroll
    for (int k = 1; k < 8; k++) r = (i == k) ? a[k] : r;
    return r;
}

// ---------------- fused attention kernel (R10 + direct CI load) -----------
// grid (64, 4, 3), block 256.
// z==0: uu2du. x = (ltile<<1)|hg; warp w: head hg*4+(w>>1), queries (w&1)*4..
//        CI loaded directly (8 consecutive l's = two aligned float4 per row).
// z==1/2: standard MHA (ta/du), x*4 = query tile, warp w = head w.
__global__ __launch_bounds__(256,2) void attn_kernel(const float* __restrict__ uu_w,
                                                     const float* __restrict__ CI) {
    __shared__ __align__(16) float sq[8*128];
    __shared__ __align__(16) float sci0[8*512];
    __shared__ __align__(16) float sci1[8*512];
    __shared__ float swv6[128], swv7[128], sa[64], sb[64];

    int z = blockIdx.z;
    int b = blockIdx.y;
    int t = threadIdx.x, w = t >> 5, lane = t & 31;

    if (z == 0) {
        int ltile = blockIdx.x >> 1;
        int hg    = blockIdx.x & 1;
        int l0    = ltile * 8;
        int h     = hg*4 + (w >> 1);
        int lw    = (w & 1) * 4;

        const float4* q4p = (const float4*)(g_qu + ((b*LL + l0) << 7));
        for (int i = t; i < 256; i += 256) ((float4*)sq)[i] = q4p[i];
        // direct CI column gather: CI[b][n][l0..l0+7] and CI[b][n][256+l0..+7]
        for (int n = t; n < 512; n += 256) {
            const float* src = CI + ((((b<<9) + n) << 9) + l0);
            float4 a0 = *(const float4*)(src);
            float4 a1 = *(const float4*)(src + 4);
            float4 c0 = *(const float4*)(src + 256);
            float4 c1 = *(const float4*)(src + 260);
            sci0[0*512+n]=a0.x; sci0[1*512+n]=a0.y; sci0[2*512+n]=a0.z; sci0[3*512+n]=a0.w;
            sci0[4*512+n]=a1.x; sci0[5*512+n]=a1.y; sci0[6*512+n]=a1.z; sci0[7*512+n]=a1.w;
            sci1[0*512+n]=c0.x; sci1[1*512+n]=c0.y; sci1[2*512+n]=c0.z; sci1[3*512+n]=c0.w;
            sci1[4*512+n]=c1.x; sci1[5*512+n]=c1.y; sci1[6*512+n]=c1.z; sci1[7*512+n]=c1.w;
        }
        if (t < 128) {
            swv6[t] = uu_w[(256 + t)*128 + 126];
            swv7[t] = uu_w[(256 + t)*128 + 127];
        }
        __syncthreads();
        if (t < 64) {
            int l = t >> 3, hh = t & 7;
            float A = 0.f, Bv = 0.f;
            #pragma unroll
            for (int d = 0; d < 16; d++) {
                float qv = sq[(l<<7) + (hh<<4) + d];
                A  += qv * uu_w[(128 + (hh<<4) + d)*128 + 126];
                Bv += qv * uu_w[(128 + (hh<<4) + d)*128 + 127];
            }
            sa[t] = A; sb[t] = Bv;
        }
        __syncthreads();

        float s[TLu][16];
        #pragma unroll
        for (int l = 0; l < TLu; l++)
            #pragma unroll
            for (int k = 0; k < 16; k++) s[l][k] = 0.f;
        const float* K0Th = g_K0T + (((b<<3) + h) << 4) * 512;
        #pragma unroll
        for (int d = 0; d < 16; d++) {
            float q0 = sq[((lw+0)<<7) + (h<<4) + d];
            float q1 = sq[((lw+1)<<7) + (h<<4) + d];
            float q2 = sq[((lw+2)<<7) + (h<<4) + d];
            float q3 = sq[((lw+3)<<7) + (h<<4) + d];
            const float* rp = K0Th + (d<<9) + (lane<<2);
            #pragma unroll
            for (int k4 = 0; k4 < 4; k4++) {
                float4 kv = *(const float4*)(rp + (k4<<7));
                s[0][4*k4+0]+=q0*kv.x; s[0][4*k4+1]+=q0*kv.y; s[0][4*k4+2]+=q0*kv.z; s[0][4*k4+3]+=q0*kv.w;
                s[1][4*k4+0]+=q1*kv.x; s[1][4*k4+1]+=q1*kv.y; s[1][4*k4+2]+=q1*kv.z; s[1][4*k4+3]+=q1*kv.w;
                s[2][4*k4+0]+=q2*kv.x; s[2][4*k4+1]+=q2*kv.y; s[2][4*k4+2]+=q2*kv.z; s[2][4*k4+3]+=q2*kv.w;
                s[3][4*k4+0]+=q3*kv.x; s[3][4*k4+1]+=q3*kv.y; s[3][4*k4+2]+=q3*kv.z; s[3][4*k4+3]+=q3*kv.w;
            }
        }

        float rsum[TLu], rc0[TLu], rc1[TLu];
        #pragma unroll
        for (int l = 0; l < TLu; l++) {
            int lloc = lw + l;
            float av = sa[(lloc<<3) + h], bv = sb[(lloc<<3) + h];
            float m = -1e30f;
            #pragma unroll
            for (int k4 = 0; k4 < 4; k4++) {
                float4 c0 = *(const float4*)&sci0[(lloc<<9) + (k4<<7) + (lane<<2)];
                float4 c1 = *(const float4*)&sci1[(lloc<<9) + (k4<<7) + (lane<<2)];
                float* sp = &s[l][k4<<2];
                sp[0] = (sp[0] + c0.x*av + c1.x*bv) * 0.25f;
                sp[1] = (sp[1] + c0.y*av + c1.y*bv) * 0.25f;
                sp[2] = (sp[2] + c0.z*av + c1.z*bv) * 0.25f;
                sp[3] = (sp[3] + c0.w*av + c1.w*bv) * 0.25f;
                m = fmaxf(m, fmaxf(fmaxf(sp[0], sp[1]), fmaxf(sp[2], sp[3])));
            }
            #pragma unroll
            for (int o = 16; o > 0; o >>= 1) m = fmaxf(m, __shfl_xor_sync(0xffffffffu, m, o));
            float su = 0.f, cs0 = 0.f, cs1 = 0.f;
            #pragma unroll
            for (int k4 = 0; k4 < 4; k4++) {
                float4 c0 = *(const float4*)&sci0[(lloc<<9) + (k4<<7) + (lane<<2)];
                float4 c1 = *(const float4*)&sci1[(lloc<<9) + (k4<<7) + (lane<<2)];
                float* sp = &s[l][k4<<2];
                float e0 = __expf(sp[0]-m), e1 = __expf(sp[1]-m);
                float e2 = __expf(sp[2]-m), e3 = __expf(sp[3]-m);
                sp[0]=e0; sp[1]=e1; sp[2]=e2; sp[3]=e3;
                su  += (e0+e1) + (e2+e3);
                cs0 += e0*c0.x + e1*c0.y + e2*c0.z + e3*c0.w;
                cs1 += e0*c1.x + e1*c1.y + e2*c1.z + e3*c1.w;
            }
            #pragma unroll
            for (int o = 16; o > 0; o >>= 1) {
                su  += __shfl_xor_sync(0xffffffffu, su,  o);
                cs0 += __shfl_xor_sync(0xffffffffu, cs0, o);
                cs1 += __shfl_xor_sync(0xffffffffu, cs1, o);
            }
            rsum[l] = su; rc0[l] = cs0; rc1[l] = cs1;
        }

        const float* V0Th = g_V0T + (((b<<3) + h) << 4) * 512;
        #pragma unroll
        for (int half = 0; half < 2; half++) {
            float acc[TLu][8];
            #pragma unroll
            for (int l = 0; l < TLu; l++)
                #pragma unroll
                for (int dd = 0; dd < 8; dd++) acc[l][dd] = 0.f;
            #pragma unroll
            for (int dd = 0; dd < 8; dd++) {
                const float* vp = V0Th + (((half<<3)+dd)<<9) + (lane<<2);
                #pragma unroll
                for (int k4 = 0; k4 < 4; k4++) {
                    float4 v4 = *(const float4*)(vp + (k4<<7));
                    #pragma unroll
                    for (int l = 0; l < TLu; l++) {
                        float* sp = &s[l][k4<<2];
                        acc[l][dd] += sp[0]*v4.x + sp[1]*v4.y + sp[2]*v4.z + sp[3]*v4.w;
                    }
                }
            }
            #pragma unroll
            for (int o = 16; o > 0; o >>= 1)
                #pragma unroll
                for (int l = 0; l < TLu; l++)
                    #pragma unroll
                    for (int dd = 0; dd < 8; dd++)
                        acc[l][dd] += __shfl_xor_sync(0xffffffffu, acc[l][dd], o);
            if (lane < 8) {
                int d = (half<<3) + lane;
                #pragma unroll
                for (int l = 0; l < TLu; l++) {
                    float av = pick8(acc[l], lane);
                    float ov = (av + rc0[l]*swv6[(h<<4)+d] + rc1[l]*swv7[(h<<4)+d]) / rsum[l];
                    g_att_u[((b*LL + l0 + lw + l) << 7) + (h<<4) + d] = ov;
                }
            }
        }
    } else {
        int l0 = blockIdx.x * 4;
        int h  = w;
        const float* Q  = (z==1) ? g_qt  : g_qd;
        const float* KT = (z==1) ? g_ktT : g_kdT;
        const float* VT = (z==1) ? g_vtT : g_vdT;
        float* O        = (z==1) ? g_att_t : g_att_d;

        const float4* q4p = (const float4*)(Q + ((b*LL + l0) << 7));
        for (int i = t; i < 128; i += 256) ((float4*)sq)[i] = q4p[i];
        __syncthreads();

        float s[TLu][8];
        #pragma unroll
        for (int l = 0; l < TLu; l++)
            #pragma unroll
            for (int k = 0; k < 8; k++) s[l][k] = 0.f;
        const float* KTh = KT + (((b<<3) + h) << 4) * 256;
        #pragma unroll
        for (int d = 0; d < 16; d++) {
            float q0 = sq[(0<<7) + (h<<4) + d];
            float q1 = sq[(1<<7) + (h<<4) + d];
            float q2 = sq[(2<<7) + (h<<4) + d];
            float q3 = sq[(3<<7) + (h<<4) + d];
            const float* rp = KTh + (d<<8) + (lane<<2);
            #pragma unroll
            for (int k4 = 0; k4 < 2; k4++) {
                float4 kv = *(const float4*)(rp + (k4<<7));
                s[0][4*k4+0]+=q0*kv.x; s[0][4*k4+1]+=q0*kv.y; s[0][4*k4+2]+=q0*kv.z; s[0][4*k4+3]+=q0*kv.w;
                s[1][4*k4+0]+=q1*kv.x; s[1][4*k4+1]+=q1*kv.y; s[1][4*k4+2]+=q1*kv.z; s[1][4*k4+3]+=q1*kv.w;
                s[2][4*k4+0]+=q2*kv.x; s[2][4*k4+1]+=q2*kv.y; s[2][4*k4+2]+=q2*kv.z; s[2][4*k4+3]+=q2*kv.w;
                s[3][4*k4+0]+=q3*kv.x; s[3][4*k4+1]+=q3*kv.y; s[3][4*k4+2]+=q3*kv.z; s[3][4*k4+3]+=q3*kv.w;
            }
        }
        float rsum[TLu];
        #pragma unroll
        for (int l = 0; l < TLu; l++) {
            float m = -1e30f;
            #pragma unroll
            for (int k = 0; k < 8; k++) { s[l][k] *= 0.25f; m = fmaxf(m, s[l][k]); }
            #pragma unroll
            for (int o = 16; o > 0; o >>= 1) m = fmaxf(m, __shfl_xor_sync(0xffffffffu, m, o));
            float su = 0.f;
            #pragma unroll
            for (int k = 0; k < 8; k++) { float e = __expf(s[l][k]-m); s[l][k] = e; su += e; }
            #pragma unroll
            for (int o = 16; o > 0; o >>= 1) su += __shfl_xor_sync(0xffffffffu, su, o);
            rsum[l] = su;
        }
        const float* VTh = VT + (((b<<3) + h) << 4) * 256;
        #pragma unroll
        for (int half = 0; half < 2; half++) {
            float acc[TLu][8];
            #pragma unroll
            for (int l = 0; l < TLu; l++)
                #pragma unroll
                for (int dd = 0; dd < 8; dd++) acc[l][dd] = 0.f;
            #pragma unroll
            for (int dd = 0; dd < 8; dd++) {
                const float* vp = VTh + (((half<<3)+dd)<<8) + (lane<<2);
                #pragma unroll
                for (int k4 = 0; k4 < 2; k4++) {
                    float4 v4 = *(const float4*)(vp + (k4<<7));
                    #pragma unroll
                    for (int l = 0; l < TLu; l++) {
                        float* sp = &s[l][k4<<2];
                        acc[l][dd] += sp[0]*v4.x + sp[1]*v4.y + sp[2]*v4.z + sp[3]*v4.w;
                    }
                }
            }
            #pragma unroll
            for (int o = 16; o > 0; o >>= 1)
                #pragma unroll
                for (int l = 0; l < TLu; l++)
                    #pragma unroll
                    for (int dd = 0; dd < 8; dd++)
                        acc[l][dd] += __shfl_xor_sync(0xffffffffu, acc[l][dd], o);
            if (lane < 8) {
                int d = (half<<3) + lane;
                #pragma unroll
                for (int l = 0; l < TLu; l++) {
                    float av = pick8(acc[l], lane);
                    O[((b*LL + l0 + l) << 7) + (h<<4) + d] = av / rsum[l];
                }
            }
        }
    }
}

// ---------------- final partial GEMM: K-split + vectorized (R10) ----------
__global__ __launch_bounds__(256) void final_gemm_kernel() {
    __shared__ __align__(16) float As[32*36];
    __shared__ __align__(16) float Ws[32*132];
    int sidx = blockIdx.y;
    int kz   = blockIdx.z;
    const float* A = (sidx==0) ? g_att_u : (sidx==1) ? g_att_t : g_att_d;
    const float* W = (sidx==0) ? g_Mu   : (sidx==1) ? g_Mt   : g_Md;
    float* P = g_part + (kz*3 + sidx) * (BLr*EE);
    int row0 = blockIdx.x << 5;
    int t = threadIdx.x;
    int ti = t >> 5, tj = t & 31;
    float acc[4][4] = {};
    int kc0 = kz << 6;
    for (int kc = kc0; kc < kc0 + 64; kc += 32) {
        #pragma unroll
        for (int i = 0; i < 4; i++) {
            int idx = t + i*256; int r = idx>>5, c = idx&31;
            As[r*36 + c] = A[(row0 + r)*128 + kc + c];
        }
        #pragma unroll
        for (int i = 0; i < 16; i++) {
            int idx = t + i*256; int col = idx>>5, kk = idx&31;
            Ws[kk*132 + col] = W[col*128 + kc + kk];
        }
        __syncthreads();
        #pragma unroll
        for (int kkb = 0; kkb < 8; kkb++) {
            float4 w0 = *(const float4*)&Ws[(kkb*4+0)*132 + (tj<<2)];
            float4 w1 = *(const float4*)&Ws[(kkb*4+1)*132 + (tj<<2)];
            float4 w2 = *(const float4*)&Ws[(kkb*4+2)*132 + (tj<<2)];
            float4 w3 = *(const float4*)&Ws[(kkb*4+3)*132 + (tj<<2)];
            #pragma unroll
            for (int i = 0; i < 4; i++) {
                float4 a4 = *(const float4*)&As[(ti*4+i)*36 + (kkb<<2)];
                acc[i][0] += a4.x*w0.x + a4.y*w1.x + a4.z*w2.x + a4.w*w3.x;
                acc[i][1] += a4.x*w0.y + a4.y*w1.y + a4.z*w2.y + a4.w*w3.y;
                acc[i][2] += a4.x*w0.z + a4.y*w1.z + a4.z*w2.z + a4.w*w3.z;
                acc[i][3] += a4.x*w0.w + a4.y*w1.w + a4.z*w2.w + a4.w*w3.w;
            }
        }
        __syncthreads();
    }
    #pragma unroll
    for (int i = 0; i < 4; i++) {
        int r = row0 + ti*4 + i;
        float4 o;
        o.x = acc[i][0]; o.y = acc[i][1]; o.z = acc[i][2]; o.w = acc[i][3];
        *(float4*)&P[r*128 + (tj<<2)] = o;
    }
}

// ---------------- BN stats (coalesced, 6 partials) ------------------------
__global__ __launch_bounds__(256) void bn_stats_kernel() {
    __shared__ float sh1[256], sh2[256];
    int t = threadIdx.x;
    int base = blockIdx.x * 1024;
    float s1 = 0.f, s2 = 0.f;
    #pragma unroll
    for (int i = 0; i < 4; i++) {
        int idx = base + i*256 + t;
        float v = g_part[idx]          + g_part[131072 + idx] + g_part[262144 + idx]
                + g_part[393216 + idx] + g_part[524288 + idx] + g_part[655360 + idx];
        s1 += v; s2 += v*v;
    }
    sh1[t] = s1; sh2[t] = s2;
    __syncthreads();
    if (t < 128) {
        atomicAdd(&g_s1[t], sh1[t] + sh1[t+128]);
        atomicAdd(&g_s2[t], sh2[t] + sh2[t+128]);
    }
}

// ---------------- BN apply + ReLU (combines 6 partials on the fly) --------
__global__ __launch_bounds__(512) void bn_apply_kernel(
    const float* __restrict__ gamma, const float* __restrict__ beta,
    float* __restrict__ out)
{
    int idx = blockIdx.x*512 + threadIdx.x;
    int c = idx & 127;
    float mean = g_s1[c] * (1.f/1024.f);
    float var  = g_s2[c] * (1.f/1024.f) - mean*mean;
    float istd = rsqrtf(var + 1e-5f);
    float y = g_part[idx]          + g_part[131072 + idx] + g_part[262144 + idx]
            + g_part[393216 + idx] + g_part[524288 + idx] + g_part[655360 + idx];
    float v = (y - mean) * istd * gamma[c] + beta[c];
    out[idx] = fmaxf(v, 0.f);
}

// ---------------- host launch --------------------------------------------
extern "C" void kernel_launch(void* const* d_in, const int* in_sizes, int n_in,
                              void* d_out, int out_size) {
    const float* UU    = (const float*)d_in[0];
    const float* DU    = (const float*)d_in[1];
    const float* TA    = (const float*)d_in[2];
    const float* CI    = (const float*)d_in[3];
    const float* uu_w  = (const float*)d_in[4];
    const float* uu_b  = (const float*)d_in[5];
    const float* uu_ow = (const float*)d_in[6];
    const float* ta_w  = (const float*)d_in[8];
    const float* ta_b  = (const float*)d_in[9];
    const float* ta_ow = (const float*)d_in[10];
    const float* du_w  = (const float*)d_in[12];
    const float* du_b  = (const float*)d_in[13];
    const float* du_ow = (const float*)d_in[14];
    const float* dim_w = (const float*)d_in[16];
    const float* gamma = (const float*)d_in[18];
    const float* beta  = (const float*)d_in[19];
    float* out = (float*)d_out;

    proj_all_kernel<<<dim3(32,12), 256>>>(DU, TA, UU, uu_w, uu_b, ta_w, ta_b,
                                          du_w, du_b, uu_ow, ta_ow, du_ow, dim_w);
    attn_kernel<<<dim3(64,4,3), 256>>>(uu_w, CI);
    final_gemm_kernel<<<dim3(32,3,2), 256>>>();
    bn_stats_kernel<<<128,256>>>();
    bn_apply_kernel<<<256,512>>>(gamma, beta, out);
}